// round 1
// baseline (speedup 1.0000x reference)
#include <cuda_runtime.h>

// MyLSTM: 2-layer LSTM (INP=3, H=4) + per-timestep MLP head.
// B=4096 sequences, T=1024 steps. 4 threads per sequence (one per hidden
// unit), all weights in registers, hidden state exchanged via quad shuffles.

#define BATCH 4096
#define SEQT  1024

__device__ __forceinline__ float rcp_fast(float x) {
    float r;
    asm("rcp.approx.f32 %0, %1;" : "=f"(r) : "f"(x));
    return r;
}

// sigmoid(x) = 1/(1+e^-x); safe at both extremes (e->inf => 0, e->0 => 1)
__device__ __forceinline__ float sigmoid_f(float x) {
    float e = __expf(-x);
    return rcp_fast(1.0f + e);
}

// tanh(x) = sign(x) * (1 - 2/(e^{2|x|}+1)); safe for large |x| (rcp(inf)=0)
__device__ __forceinline__ float tanh_f(float x) {
    float a = fabsf(x);
    float e = __expf(2.0f * a);
    float r = 1.0f - 2.0f * rcp_fast(e + 1.0f);
    return copysignf(r, x);
}

extern "C" __global__ void __launch_bounds__(128, 1)
lstm_mlp_kernel(const float* __restrict__ x,
                const float* __restrict__ Wih0, const float* __restrict__ Whh0,
                const float* __restrict__ bih0, const float* __restrict__ bhh0,
                const float* __restrict__ Wih1, const float* __restrict__ Whh1,
                const float* __restrict__ bih1, const float* __restrict__ bhh1,
                const float* __restrict__ W1,   const float* __restrict__ b1,
                const float* __restrict__ W2,   const float* __restrict__ b2,
                float* __restrict__ y)
{
    const int tid = blockIdx.x * 128 + threadIdx.x;
    const int seq = tid >> 2;   // sequence index
    const int j   = tid & 3;    // hidden-unit index handled by this thread
    if (seq >= BATCH) return;

    // ---- load this thread's weight slices into registers ----
    float wi0[4][3], wh0[4][4], wb0[4];   // layer 0, gates (i,f,g,o) row g*4+j
    float wi1[4][4], wh1[4][4], wb1[4];   // layer 1
#pragma unroll
    for (int g = 0; g < 4; ++g) {
        const int r = g * 4 + j;
#pragma unroll
        for (int k = 0; k < 3; ++k) wi0[g][k] = Wih0[r * 3 + k];
#pragma unroll
        for (int k = 0; k < 4; ++k) wh0[g][k] = Whh0[r * 4 + k];
        wb0[g] = bih0[r] + bhh0[r];
#pragma unroll
        for (int k = 0; k < 4; ++k) wi1[g][k] = Wih1[r * 4 + k];
#pragma unroll
        for (int k = 0; k < 4; ++k) wh1[g][k] = Whh1[r * 4 + k];
        wb1[g] = bih1[r] + bhh1[r];
    }
    float w1r[4];
#pragma unroll
    for (int k = 0; k < 4; ++k) w1r[k] = W1[j * 4 + k];
    const float b1j = b1[j];
    const float w2j = W2[j];
    const float b2v = b2[0];

    // ---- recurrent state ----
    float h0 = 0.0f, c0 = 0.0f, h1 = 0.0f, c1 = 0.0f;

    const float* xp = x + (size_t)seq * SEQT * 3;
    float*       yp = y + (size_t)seq * SEQT;

    const unsigned FULL = 0xFFFFFFFFu;
    const int lane = threadIdx.x & 31;
    const int qb   = lane & ~3;          // quad base lane

    for (int t = 0; t < SEQT; ++t) {
        const float x0 = xp[3 * t + 0];
        const float x1 = xp[3 * t + 1];
        const float x2 = xp[3 * t + 2];

        // ---- layer 0 ----
        float ha[4];
#pragma unroll
        for (int k = 0; k < 4; ++k) ha[k] = __shfl_sync(FULL, h0, qb + k);

        float pre[4];
#pragma unroll
        for (int g = 0; g < 4; ++g) {
            float s = wb0[g];
            s = fmaf(wi0[g][0], x0, s);
            s = fmaf(wi0[g][1], x1, s);
            s = fmaf(wi0[g][2], x2, s);
#pragma unroll
            for (int k = 0; k < 4; ++k) s = fmaf(wh0[g][k], ha[k], s);
            pre[g] = s;
        }
        {
            const float ig = sigmoid_f(pre[0]);
            const float fg = sigmoid_f(pre[1]);
            const float gg = tanh_f(pre[2]);
            const float og = sigmoid_f(pre[3]);
            c0 = fmaf(fg, c0, ig * gg);
            h0 = og * tanh_f(c0);
        }

        // ---- layer 1 (input = new h0, recurrence = old h1) ----
        float hb[4], hc[4];
#pragma unroll
        for (int k = 0; k < 4; ++k) hb[k] = __shfl_sync(FULL, h0, qb + k);
#pragma unroll
        for (int k = 0; k < 4; ++k) hc[k] = __shfl_sync(FULL, h1, qb + k);
#pragma unroll
        for (int g = 0; g < 4; ++g) {
            float s = wb1[g];
#pragma unroll
            for (int k = 0; k < 4; ++k) s = fmaf(wi1[g][k], hb[k], s);
#pragma unroll
            for (int k = 0; k < 4; ++k) s = fmaf(wh1[g][k], hc[k], s);
            pre[g] = s;
        }
        {
            const float ig = sigmoid_f(pre[0]);
            const float fg = sigmoid_f(pre[1]);
            const float gg = tanh_f(pre[2]);
            const float og = sigmoid_f(pre[3]);
            c1 = fmaf(fg, c1, ig * gg);
            h1 = og * tanh_f(c1);
        }

        // ---- MLP head: y = tanh(h1 @ W1^T + b1) @ W2^T + b2 ----
        float hd[4];
#pragma unroll
        for (int k = 0; k < 4; ++k) hd[k] = __shfl_sync(FULL, h1, qb + k);
        float s = b1j;
#pragma unroll
        for (int k = 0; k < 4; ++k) s = fmaf(w1r[k], hd[k], s);
        float v = w2j * tanh_f(s);
        v += __shfl_xor_sync(FULL, v, 1);
        v += __shfl_xor_sync(FULL, v, 2);
        if (j == 0) yp[t] = v + b2v;
    }
}

extern "C" void kernel_launch(void* const* d_in, const int* in_sizes, int n_in,
                              void* d_out, int out_size)
{
    const float* x    = (const float*)d_in[0];
    const float* Wih0 = (const float*)d_in[1];
    const float* Whh0 = (const float*)d_in[2];
    const float* bih0 = (const float*)d_in[3];
    const float* bhh0 = (const float*)d_in[4];
    const float* Wih1 = (const float*)d_in[5];
    const float* Whh1 = (const float*)d_in[6];
    const float* bih1 = (const float*)d_in[7];
    const float* bhh1 = (const float*)d_in[8];
    const float* W1   = (const float*)d_in[9];
    const float* b1   = (const float*)d_in[10];
    const float* W2   = (const float*)d_in[11];
    const float* b2   = (const float*)d_in[12];
    float* y = (float*)d_out;

    const int threads = 128;
    const int total   = BATCH * 4;          // 4 threads per sequence
    const int blocks  = (total + threads - 1) / threads;  // 128
    lstm_mlp_kernel<<<blocks, threads>>>(x, Wih0, Whh0, bih0, bhh0,
                                         Wih1, Whh1, bih1, bhh1,
                                         W1, b1, W2, b2, y);
}

// round 7
// speedup vs baseline: 4.6947x; 4.6947x over previous
#include <cuda_runtime.h>

// MyLSTM: 2-layer LSTM (INP=3, H=4) + per-timestep MLP head.
// 4 threads per sequence (one hidden unit each), weights in registers.
// tanh.approx.f32 activations, sigmoid via tanh identity with pre-halved
// gate weights. Hidden-state broadcasts reused across timesteps (2 shuffle
// rounds/step). MLP head computed redundantly in every lane (no reduce).

#define BATCH 4096
#define SEQT  1024

__device__ __forceinline__ float tanh_fast(float x) {
    float r;
    asm("tanh.approx.f32 %0, %1;" : "=f"(r) : "f"(x));
    return r;
}

// expects pre-activation already multiplied by 0.5 (weights pre-halved)
__device__ __forceinline__ float sigmoid_half(float xh) {
    return fmaf(0.5f, tanh_fast(xh), 0.5f);
}

extern "C" __global__ void __launch_bounds__(128, 1)
lstm_mlp_kernel(const float* __restrict__ x,
                const float* __restrict__ Wih0, const float* __restrict__ Whh0,
                const float* __restrict__ bih0, const float* __restrict__ bhh0,
                const float* __restrict__ Wih1, const float* __restrict__ Whh1,
                const float* __restrict__ bih1, const float* __restrict__ bhh1,
                const float* __restrict__ W1,   const float* __restrict__ b1,
                const float* __restrict__ W2,   const float* __restrict__ b2,
                float* __restrict__ y)
{
    const int tid = blockIdx.x * 128 + threadIdx.x;
    const int seq = tid >> 2;   // sequence index
    const int j   = tid & 3;    // hidden unit handled by this thread
    if (seq >= BATCH) return;

    // ---- register weights; gates i(0), f(1), o(3) pre-halved for sigmoid ----
    float wi0[4][3], wh0[4][4], wb0[4];
    float wi1[4][4], wh1[4][4], wb1[4];
#pragma unroll
    for (int g = 0; g < 4; ++g) {
        const float sc = (g == 2) ? 1.0f : 0.5f;
        const int r = g * 4 + j;
#pragma unroll
        for (int k = 0; k < 3; ++k) wi0[g][k] = sc * Wih0[r * 3 + k];
#pragma unroll
        for (int k = 0; k < 4; ++k) wh0[g][k] = sc * Whh0[r * 4 + k];
        wb0[g] = sc * (bih0[r] + bhh0[r]);
#pragma unroll
        for (int k = 0; k < 4; ++k) wi1[g][k] = sc * Wih1[r * 4 + k];
#pragma unroll
        for (int k = 0; k < 4; ++k) wh1[g][k] = sc * Whh1[r * 4 + k];
        wb1[g] = sc * (bih1[r] + bhh1[r]);
    }
    // full MLP head in every thread (redundant across the quad)
    float w1m[4][4], b1v[4], w2v[4];
#pragma unroll
    for (int k = 0; k < 4; ++k) {
#pragma unroll
        for (int m = 0; m < 4; ++m) w1m[k][m] = W1[k * 4 + m];
        b1v[k] = b1[k];
        w2v[k] = W2[k];
    }
    const float b2v = b2[0];

    // ---- state: own h/c plus broadcast copies of the full h vectors ----
    float c0 = 0.0f, c1 = 0.0f;
    float hb[4] = {0, 0, 0, 0};   // broadcast of layer-0 h (updated per step)
    float hd[4] = {0, 0, 0, 0};   // broadcast of layer-1 h (updated per step)

    const float* xp = x + (size_t)seq * SEQT * 3;
    float*       yp = y + (size_t)seq * SEQT;

    const unsigned FULL = 0xFFFFFFFFu;

    // prefetch first timestep's input
    float x0 = xp[0], x1 = xp[1], x2 = xp[2];

#pragma unroll 2
    for (int t = 0; t < SEQT; ++t) {
        // ---- layer 0: uses hb from previous step (h0[t-1]) ----
        float pre[4];
#pragma unroll
        for (int g = 0; g < 4; ++g) {
            float s = wb0[g];
            s = fmaf(wi0[g][0], x0, s);
            s = fmaf(wi0[g][1], x1, s);
            s = fmaf(wi0[g][2], x2, s);
#pragma unroll
            for (int k = 0; k < 4; ++k) s = fmaf(wh0[g][k], hb[k], s);
            pre[g] = s;
        }
        // prefetch next x while activations are in flight
        if (t + 1 < SEQT) {
            x0 = xp[3 * t + 3];
            x1 = xp[3 * t + 4];
            x2 = xp[3 * t + 5];
        }
        float h0;
        {
            const float ig = sigmoid_half(pre[0]);
            const float fg = sigmoid_half(pre[1]);
            const float gg = tanh_fast(pre[2]);
            const float og = sigmoid_half(pre[3]);
            c0 = fmaf(fg, c0, ig * gg);
            h0 = og * tanh_fast(c0);
        }
        // broadcast new h0 within the quad
#pragma unroll
        for (int k = 0; k < 4; ++k) hb[k] = __shfl_sync(FULL, h0, k, 4);

        // ---- layer 1: input = new h0 (hb), recurrence = old h1 (hd) ----
#pragma unroll
        for (int g = 0; g < 4; ++g) {
            float s = wb1[g];
#pragma unroll
            for (int k = 0; k < 4; ++k) s = fmaf(wi1[g][k], hb[k], s);
#pragma unroll
            for (int k = 0; k < 4; ++k) s = fmaf(wh1[g][k], hd[k], s);
            pre[g] = s;
        }
        float h1;
        {
            const float ig = sigmoid_half(pre[0]);
            const float fg = sigmoid_half(pre[1]);
            const float gg = tanh_fast(pre[2]);
            const float og = sigmoid_half(pre[3]);
            c1 = fmaf(fg, c1, ig * gg);
            h1 = og * tanh_fast(c1);
        }
        // broadcast new h1 within the quad
#pragma unroll
        for (int k = 0; k < 4; ++k) hd[k] = __shfl_sync(FULL, h1, k, 4);

        // ---- MLP head (redundant in every lane, no reduction shuffles) ----
        float acc = b2v;
#pragma unroll
        for (int k = 0; k < 4; ++k) {
            float s = b1v[k];
#pragma unroll
            for (int m = 0; m < 4; ++m) s = fmaf(w1m[k][m], hd[m], s);
            acc = fmaf(w2v[k], tanh_fast(s), acc);
        }
        if (j == 0) yp[t] = acc;
    }
}

extern "C" void kernel_launch(void* const* d_in, const int* in_sizes, int n_in,
                              void* d_out, int out_size)
{
    const float* x    = (const float*)d_in[0];
    const float* Wih0 = (const float*)d_in[1];
    const float* Whh0 = (const float*)d_in[2];
    const float* bih0 = (const float*)d_in[3];
    const float* bhh0 = (const float*)d_in[4];
    const float* Wih1 = (const float*)d_in[5];
    const float* Whh1 = (const float*)d_in[6];
    const float* bih1 = (const float*)d_in[7];
    const float* bhh1 = (const float*)d_in[8];
    const float* W1   = (const float*)d_in[9];
    const float* b1   = (const float*)d_in[10];
    const float* W2   = (const float*)d_in[11];
    const float* b2   = (const float*)d_in[12];
    float* y = (float*)d_out;

    const int threads = 128;
    const int total   = BATCH * 4;
    const int blocks  = (total + threads - 1) / threads;  // 128
    lstm_mlp_kernel<<<blocks, threads>>>(x, Wih0, Whh0, bih0, bhh0,
                                         Wih1, Whh1, bih1, bhh1,
                                         W1, b1, W2, b2, y);
}